// round 14
// baseline (speedup 1.0000x reference)
#include <cuda_runtime.h>
#include <cuda_fp16.h>
#include <cstdint>
#include <math.h>

#define LN   2048
#define BN_  4
#define EN   1024
#define HN   8
#define D1N  2048
#define HDN  256
#define MN   (LN*BN_)   // 8192

// ---------------- device scratch ----------------
__device__ __align__(16) __half g_x[MN*EN];
__device__ __align__(16) __half g_uw[D1N*EN], g_vw[D1N*EN], g_ow[EN*D1N];
__device__ __align__(16) __half g_u[MN*D1N];
__device__ __align__(16) __half g_vt[(size_t)32*HDN*LN];
__device__ __align__(16) __half g_a[MN*D1N];
// precomputed toeplitz A tiles: 8 heads x 62 deltas x (128x64) f16, pre-swizzled
__device__ __align__(16) __half g_tt[(size_t)HN*62*8192];

// ---------------- helpers ----------------
__device__ __forceinline__ uint32_t smem_u32(const void* p){
    uint32_t a;
    asm("{ .reg .u64 t; cvta.to.shared.u64 t, %1; cvt.u32.u64 %0, t; }" : "=r"(a) : "l"(p));
    return a;
}
#define SWZ(o) ((uint32_t)(o) ^ ((((uint32_t)(o))>>3)&0x70))

__device__ __forceinline__ uint32_t pkh(float a, float b){
    __half2 h = __floats2half2_rn(a, b);
    return *reinterpret_cast<uint32_t*>(&h);
}
__device__ __forceinline__ void ldsm4(uint32_t* r, uint32_t addr){
    asm volatile("ldmatrix.sync.aligned.m8n8.x4.shared.b16 {%0,%1,%2,%3}, [%4];"
                 : "=r"(r[0]),"=r"(r[1]),"=r"(r[2]),"=r"(r[3]) : "r"(addr));
}
__device__ __forceinline__ void mma16816(float* d, const uint32_t* a, const uint32_t* b){
    asm volatile("mma.sync.aligned.m16n8k16.row.col.f32.f16.f16.f32 "
        "{%0,%1,%2,%3}, {%4,%5,%6,%7}, {%8,%9}, {%0,%1,%2,%3};"
        : "+f"(d[0]),"+f"(d[1]),"+f"(d[2]),"+f"(d[3])
        : "r"(a[0]),"r"(a[1]),"r"(a[2]),"r"(a[3]), "r"(b[0]),"r"(b[1]));
}
__device__ __forceinline__ void cpa16(uint32_t s, const void* g){
    asm volatile("cp.async.cg.shared.global [%0], [%1], 16;" :: "r"(s), "l"(g));
}
__device__ __forceinline__ void cpa_commit(){ asm volatile("cp.async.commit_group;" ::: "memory"); }
__device__ __forceinline__ void cpa_wait0(){ asm volatile("cp.async.wait_group 0;" ::: "memory"); }
__device__ __forceinline__ void cpa_wait1(){ asm volatile("cp.async.wait_group 1;" ::: "memory"); }

// SMEM per stage: A 16K | B 16K (128x64 f16 each); 3 stages
#define TA_  0
#define TB_  16384
#define STG  32768
#define SMEM_SZ (3*STG)   // 98304, 2 CTAs/SM

// ---------------------------------------------------------------------------
__global__ void rmsnorm_k(const float* __restrict__ q, __half* __restrict__ x)
{
    int m = blockIdx.x, t = threadIdx.x;
    float4 a = reinterpret_cast<const float4*>(q + (size_t)m*EN)[t];
    float ss = a.x*a.x + a.y*a.y + a.z*a.z + a.w*a.w;
    #pragma unroll
    for (int o=16;o;o>>=1) ss += __shfl_xor_sync(0xffffffffu, ss, o);
    __shared__ float sred[8];
    if ((t&31)==0) sred[t>>5] = ss;
    __syncthreads();
    if (t<8){
        float v = sred[t];
        #pragma unroll
        for (int o=4;o;o>>=1) v += __shfl_xor_sync(0xffu, v, o);
        if (t==0) sred[0] = v;
    }
    __syncthreads();
    float inv = 1.0f / (sqrtf(sred[0]*(1.0f/EN)) + 1e-8f);
    uint2 w = make_uint2(pkh(a.x*inv, a.y*inv), pkh(a.z*inv, a.w*inv));
    *reinterpret_cast<uint2*>(x + (size_t)m*EN + t*4) = w;
}

// all three weight conversions in one launch
__global__ void cvt3_k(const float* __restrict__ w0, const float* __restrict__ w1,
                       const float* __restrict__ w2,
                       __half* __restrict__ o0, __half* __restrict__ o1,
                       __half* __restrict__ o2)
{
    const int per = (D1N*EN)/4;   // 524288
    int i = blockIdx.x*256 + threadIdx.x;
    int sel = i / per, loc = i - sel*per;
    if (sel >= 3) return;
    const float* w = sel==0 ? w0 : (sel==1 ? w1 : w2);
    __half* o      = sel==0 ? o0 : (sel==1 ? o1 : o2);
    float4 a = reinterpret_cast<const float4*>(w)[loc];
    reinterpret_cast<uint2*>(o)[loc] = make_uint2(pkh(a.x,a.y), pkh(a.z,a.w));
}

// ---------------------------------------------------------------------------
// Precompute toeplitz A tiles (128x64 f16, SW128-swizzled) directly from
// pos/zero/neg. Strip element i (0..190) is t[r], r = (ti-31)*64 + i - 63.
// ---------------------------------------------------------------------------
__global__ void toeptiles_k(const float* __restrict__ pos, const float* __restrict__ zero,
                            const float* __restrict__ neg)
{
    __shared__ float sT[192];
    int ti = blockIdx.x, h = blockIdx.y, tid = threadIdx.x;
    if (tid < 191){
        int r = (ti-31)*64 + tid - 63;
        float v;
        if (r > 0)      v = pos[h*(LN-1) + r - 1];
        else if (r < 0) v = neg[h*(LN-1) - r - 1];
        else            v = zero[h];
        sT[tid] = v;
    }
    __syncthreads();
    char* dst = (char*)g_tt + (((size_t)h*62 + ti)*8192)*2;
    #pragma unroll
    for (int it=0;it<4;it++){
        int idx = it*256+tid, m = idx>>3, k8 = (idx&7)<<3;
        int base = m + 63 - k8;
        uint32_t so = SWZ(m*128 + k8*2);
        uint32_t w0 = pkh(sT[base],   sT[base-1]);
        uint32_t w1 = pkh(sT[base-2], sT[base-3]);
        uint32_t w2 = pkh(sT[base-4], sT[base-5]);
        uint32_t w3 = pkh(sT[base-6], sT[base-7]);
        *(uint4*)(dst+so) = make_uint4(w0,w1,w2,w3);
    }
}

// ---------------------------------------------------------------------------
// MMA core: 128x128 tile, 8 warps as 2(m)x4(n), warp tile 64x32.
// Software-pipelined: B loaded per ks, A double-buffered across mi.
// Live fragment regs: 8 (B) + 8 (A x2) = 16 (was 24).
// ---------------------------------------------------------------------------
struct Acc { float a[4][4][4]; };

__device__ __forceinline__ void mma_stage(Acc& A, uint32_t base, int wm0, int wn0, int lid)
{
    int g = lid>>3;
    int arow = ((lid>>3)&1)*8 + (lid&7);
    int acol = ((lid>>4)&1)*8;
    int brow = (g>>1)*8 + (lid&7);
    int bcol = (g&1)*8;
    #pragma unroll
    for (int ks=0;ks<4;ks++){
        uint32_t bf_[2][4];
        ldsm4(bf_[0], base+TB_+SWZ((wn0   +brow)*128 + (ks*16+bcol)*2));
        ldsm4(bf_[1], base+TB_+SWZ((wn0+16+brow)*128 + (ks*16+bcol)*2));
        uint32_t af[2][4];
        ldsm4(af[0], base+TA_+SWZ((wm0+arow)*128 + (ks*16+acol)*2));
        #pragma unroll
        for (int mi=0;mi<4;mi++){
            if (mi < 3)
                ldsm4(af[(mi+1)&1], base+TA_+SWZ((wm0+(mi+1)*16+arow)*128 + (ks*16+acol)*2));
            #pragma unroll
            for (int np=0;np<2;np++){
                mma16816(A.a[mi][2*np+0], af[mi&1], &bf_[np][0]);
                mma16816(A.a[mi][2*np+1], af[mi&1], &bf_[np][2]);
            }
        }
    }
}

#define ACC_INIT(acc) \
    _Pragma("unroll") for (int i=0;i<4;i++) \
    _Pragma("unroll") for (int j=0;j<4;j++) \
    _Pragma("unroll") for (int r=0;r<4;r++) acc.a[i][j][r] = 0.f;

// ---------------------------------------------------------------------------
// Pipelined fp16 GEMM, tile 128x128, K-chunk 64, 3-stage cp.async.
// EPI 0: silu(acc+bias) -> f16 row-major.
// EPI 1: acc+bias+resid -> f32 row-major.
// EPI 2: silu(acc+bias) -> f16 written TRANSPOSED into vt layout
//        [(h*4+b)*256+d][l]  (m = l*4+b, n = h*256+d).
// ---------------------------------------------------------------------------
template<int EPI>
__global__ void __launch_bounds__(256, 2)
gemm_k(const __half* __restrict__ Ah, const __half* __restrict__ Bh,
       const float* __restrict__ bias, const float* __restrict__ resid,
       void* __restrict__ Cv, int K, int Nld)
{
    extern __shared__ char smem[];
    const uint32_t sb = smem_u32(smem);
    int tid = threadIdx.x, wid = tid>>5, lid = tid&31;
    int i0 = blockIdx.y*128, n0 = blockIdx.x*128;
    int wm0 = (wid>>2)*64, wn0 = (wid&3)*32;
    Acc acc; ACC_INIT(acc);

    int lr = tid>>3, lq = tid&7;
    uint32_t soT = SWZ(lr*128 + lq*16);

    auto load_chunk = [&](int c, int st){
        uint32_t bs = sb + st*STG;
        int kt = c<<6;
        #pragma unroll
        for (int it=0;it<4;it++){
            int r = lr + it*32;
            uint32_t so = soT + it*(32*128);
            cpa16(bs+TA_+so, Ah + (size_t)(i0 + r)*K + kt + lq*8);
            cpa16(bs+TB_+so, Bh + (size_t)(n0 + r)*K + kt + lq*8);
        }
        cpa_commit();
    };

    const int nch = K>>6;
    load_chunk(0, 0);
    if (nch > 1) load_chunk(1, 1);
    for (int c=0;c<nch;c++){
        if (c+1 < nch) cpa_wait1(); else cpa_wait0();
        __syncthreads();
        if (c+2 < nch) load_chunk(c+2, (c+2)%3);
        mma_stage(acc, sb + (c%3)*STG, wm0, wn0, lid);
    }

    if (EPI==2){
        // stage silu output into smem (row stride 136 halves), then write transposed
        __syncthreads();   // everyone done reading fragments
        __half* ts = (__half*)smem;
        #pragma unroll
        for (int mi=0;mi<4;mi++)
            #pragma unroll
            for (int ni=0;ni<4;ni++){
                int nn = wn0 + ni*8 + 2*(lid&3);
                #pragma unroll
                for (int half_=0;half_<2;half_++){
                    int ml = wm0 + mi*16 + (lid>>2) + half_*8;
                    float s0 = acc.a[mi][ni][2*half_+0] + bias[n0+nn];
                    float s1 = acc.a[mi][ni][2*half_+1] + bias[n0+nn+1];
                    s0 = s0 / (1.0f + __expf(-s0));
                    s1 = s1 / (1.0f + __expf(-s1));
                    *(uint32_t*)(ts + ml*136 + nn) = pkh(s0, s1);
                }
            }
        __syncthreads();
        int h = n0 >> 8, dbase = n0 & 255;
        int l0 = i0 >> 2;                      // 32-aligned
        __half* Vt = (__half*)Cv;
        #pragma unroll
        for (int k=0;k<2;k++){
            int idx = tid + k*256;             // 0..511 -> (b, n_local)
            int nl = idx & 127, b = idx >> 7;
            uint32_t buf[16];
            #pragma unroll
            for (int w=0;w<16;w++){
                __half a = ts[((2*w  )*4 + b)*136 + nl];
                __half c = ts[((2*w+1)*4 + b)*136 + nl];
                buf[w] = (uint32_t)__half_as_ushort(a) | ((uint32_t)__half_as_ushort(c)<<16);
            }
            size_t off = ((size_t)(h*4 + b)*HDN + dbase + nl)*LN + l0;
            uint4* dp = (uint4*)(Vt + off);
            #pragma unroll
            for (int w=0;w<4;w++) dp[w] = make_uint4(buf[4*w],buf[4*w+1],buf[4*w+2],buf[4*w+3]);
        }
        return;
    }

    #pragma unroll
    for (int mi=0;mi<4;mi++)
        #pragma unroll
        for (int ni=0;ni<4;ni++){
            int nn = n0 + wn0 + ni*8 + 2*(lid&3);
            #pragma unroll
            for (int half_=0;half_<2;half_++){
                int m = i0 + wm0 + mi*16 + (lid>>2) + half_*8;
                float v0 = acc.a[mi][ni][2*half_+0], v1 = acc.a[mi][ni][2*half_+1];
                if (EPI==0){
                    float s0 = v0 + bias[nn], s1 = v1 + bias[nn+1];
                    s0 = s0 / (1.0f + __expf(-s0)); s1 = s1 / (1.0f + __expf(-s1));
                    *(uint32_t*)((__half*)Cv + (size_t)m*Nld + nn) = pkh(s0, s1);
                } else {
                    const float* rp = resid + (size_t)m*Nld + nn;
                    float o0 = v0 + bias[nn] + rp[0], o1 = v1 + bias[nn+1] + rp[1];
                    *(float2*)((float*)Cv + (size_t)m*Nld + nn) = make_float2(o0, o1);
                }
            }
        }
}

// ---------------------------------------------------------------------------
// Pipelined toeplitz GEMM: A from precomputed f16 tiles, B from vt.
// Tile 128(l) x 128(d), K-chunk 64 over j, 32 chunks, fused gating epilogue.
// ---------------------------------------------------------------------------
__global__ void __launch_bounds__(256, 2)
toep_k(const __half* __restrict__ Vt, const __half* __restrict__ U,
       __half* __restrict__ Ao)
{
    extern __shared__ char smem[];
    const uint32_t sb = smem_u32(smem);
    int tid = threadIdx.x, wid = tid>>5, lid = tid&31;
    int s = blockIdx.z, h = s>>2, b = s&3;
    int i0 = blockIdx.y*128;
    int d0 = blockIdx.x*128;
    int wm0 = (wid>>2)*64, wn0 = (wid&3)*32;
    const __half* vt = Vt + (size_t)s*HDN*LN + (size_t)d0*LN;
    Acc acc; ACC_INIT(acc);

    int lr = tid>>3, lq = tid&7;
    uint32_t soT = SWZ(lr*128 + lq*16);
    int tibase = (blockIdx.y<<1) + 31;

    auto load_chunk = [&](int c, int st){
        uint32_t bs = sb + st*STG;
        int j0 = c<<6;
        const char* th = (const char*)g_tt + (((size_t)h*62 + (tibase - c))*8192)*2;
        #pragma unroll
        for (int it=0;it<4;it++){
            uint32_t lin = (uint32_t)(it*256+tid)*16;   // verbatim 16KB tile copy
            cpa16(bs+TA_+lin, th+lin);
            int r = lr + it*32;
            uint32_t so = soT + it*(32*128);
            cpa16(bs+TB_+so, vt + (size_t)r*LN + j0 + lq*8);
        }
        cpa_commit();
    };

    load_chunk(0, 0);
    load_chunk(1, 1);
    for (int c=0;c<32;c++){
        if (c+1 < 32) cpa_wait1(); else cpa_wait0();
        __syncthreads();
        if (c+2 < 32) load_chunk(c+2, (c+2)%3);
        mma_stage(acc, sb + (c%3)*STG, wm0, wn0, lid);
    }

    #pragma unroll
    for (int mi=0;mi<4;mi++)
        #pragma unroll
        for (int ni=0;ni<4;ni++){
            int d = d0 + wn0 + ni*8 + 2*(lid&3);
            #pragma unroll
            for (int half_=0;half_<2;half_++){
                int m = i0 + wm0 + mi*16 + (lid>>2) + half_*8;
                size_t off = ((size_t)m*BN_ + b)*D1N + h*HDN + d;
                __half2 u2 = *(const __half2*)(U + off);
                float a0 = acc.a[mi][ni][2*half_+0] * __half2float(u2.x);
                float a1 = acc.a[mi][ni][2*half_+1] * __half2float(u2.y);
                *(uint32_t*)(Ao + off) = pkh(a0, a1);
            }
        }
}

// ---------------------------------------------------------------------------
extern "C" void kernel_launch(void* const* d_in, const int* in_sizes, int n_in,
                              void* d_out, int out_size)
{
    const float* q   = (const float*)d_in[0];
    const float* u_w = (const float*)d_in[3];
    const float* u_b = (const float*)d_in[4];
    const float* v_w = (const float*)d_in[5];
    const float* v_b = (const float*)d_in[6];
    const float* o_w = (const float*)d_in[7];
    const float* o_b = (const float*)d_in[8];
    const float* pos = (const float*)d_in[9];
    const float* zer = (const float*)d_in[10];
    const float* neg = (const float*)d_in[11];
    float* out = (float*)d_out;

    cudaFuncSetAttribute(gemm_k<0>, cudaFuncAttributeMaxDynamicSharedMemorySize, SMEM_SZ);
    cudaFuncSetAttribute(gemm_k<1>, cudaFuncAttributeMaxDynamicSharedMemorySize, SMEM_SZ);
    cudaFuncSetAttribute(gemm_k<2>, cudaFuncAttributeMaxDynamicSharedMemorySize, SMEM_SZ);
    cudaFuncSetAttribute(toep_k,    cudaFuncAttributeMaxDynamicSharedMemorySize, SMEM_SZ);

    void *p;
    #define SYM(v, sym) cudaGetSymbolAddress(&p, sym); auto* v = (decltype(&sym[0]))p;
    SYM(xg,  g_x);
    SYM(uw,  g_uw); SYM(vw,  g_vw); SYM(ow,  g_ow);
    SYM(ug,  g_u);
    SYM(vt,  g_vt); SYM(ag,  g_a);
    #undef SYM

    rmsnorm_k<<<MN, 256>>>(q, xg);
    cvt3_k<<<(3*(D1N*EN/4)+255)/256, 256>>>(u_w, v_w, o_w, uw, vw, ow);
    toeptiles_k<<<dim3(62, HN), 256>>>(pos, zer, neg);
    gemm_k<0><<<dim3(D1N/128, MN/128), 256, SMEM_SZ>>>(xg, uw, u_b, nullptr, ug, EN, D1N);
    gemm_k<2><<<dim3(D1N/128, MN/128), 256, SMEM_SZ>>>(xg, vw, v_b, nullptr, vt, EN, D1N);
    toep_k<<<dim3(HDN/128, LN/128, 32), 256, SMEM_SZ>>>(vt, ug, ag);
    gemm_k<1><<<dim3(EN/128, MN/128), 256, SMEM_SZ>>>(ag, ow, o_b, q, out, D1N, EN);
}

// round 15
// speedup vs baseline: 1.0405x; 1.0405x over previous
#include <cuda_runtime.h>
#include <cuda_fp16.h>
#include <cstdint>
#include <math.h>

#define LN   2048
#define BN_  4
#define EN   1024
#define HN   8
#define D1N  2048
#define HDN  256
#define MN   (LN*BN_)   // 8192

// ---------------- device scratch ----------------
__device__ __align__(16) __half g_x[MN*EN];
__device__ __align__(16) __half g_uw[D1N*EN], g_vw[D1N*EN], g_ow[EN*D1N];
__device__ __align__(16) __half g_u[MN*D1N];
__device__ __align__(16) __half g_vt[(size_t)32*HDN*LN];
__device__ __align__(16) __half g_a[MN*D1N];
// precomputed toeplitz A tiles: 8 heads x 62 deltas x (128x64) f16, pre-swizzled
__device__ __align__(16) __half g_tt[(size_t)HN*62*8192];

// ---------------- helpers ----------------
__device__ __forceinline__ uint32_t smem_u32(const void* p){
    uint32_t a;
    asm("{ .reg .u64 t; cvta.to.shared.u64 t, %1; cvt.u32.u64 %0, t; }" : "=r"(a) : "l"(p));
    return a;
}
#define SWZ(o) ((uint32_t)(o) ^ ((((uint32_t)(o))>>3)&0x70))

__device__ __forceinline__ uint32_t pkh(float a, float b){
    __half2 h = __floats2half2_rn(a, b);
    return *reinterpret_cast<uint32_t*>(&h);
}
__device__ __forceinline__ void ldsm4(uint32_t* r, uint32_t addr){
    asm volatile("ldmatrix.sync.aligned.m8n8.x4.shared.b16 {%0,%1,%2,%3}, [%4];"
                 : "=r"(r[0]),"=r"(r[1]),"=r"(r[2]),"=r"(r[3]) : "r"(addr));
}
__device__ __forceinline__ void mma16816(float* d, const uint32_t* a, const uint32_t* b){
    asm volatile("mma.sync.aligned.m16n8k16.row.col.f32.f16.f16.f32 "
        "{%0,%1,%2,%3}, {%4,%5,%6,%7}, {%8,%9}, {%0,%1,%2,%3};"
        : "+f"(d[0]),"+f"(d[1]),"+f"(d[2]),"+f"(d[3])
        : "r"(a[0]),"r"(a[1]),"r"(a[2]),"r"(a[3]), "r"(b[0]),"r"(b[1]));
}
__device__ __forceinline__ void cpa16(uint32_t s, const void* g){
    asm volatile("cp.async.cg.shared.global [%0], [%1], 16;" :: "r"(s), "l"(g));
}
__device__ __forceinline__ void cpa_commit(){ asm volatile("cp.async.commit_group;" ::: "memory"); }
__device__ __forceinline__ void cpa_wait0(){ asm volatile("cp.async.wait_group 0;" ::: "memory"); }
__device__ __forceinline__ void cpa_wait1(){ asm volatile("cp.async.wait_group 1;" ::: "memory"); }

// SMEM per stage: A 16K | B 16K (128x64 f16 each); 3 stages
#define TA_  0
#define TB_  16384
#define STG  32768
#define SMEM_SZ (3*STG)   // 98304, 2 CTAs/SM

// ---------------------------------------------------------------------------
// Fused prep: blocks [0,8192) rmsnorm; [8192,14336) weight cvt; [14336,14832)
// toeplitz tile build. All independent; one launch overlaps their memory traffic.
// ---------------------------------------------------------------------------
#define PREP_RMS   MN                      // 8192
#define PREP_CVT   (PREP_RMS + 6144)       // 14336 (3 * 2048 blocks of 1024 float4... 3*2M/4/256 = 6144)
#define PREP_TT    (PREP_CVT + 62*HN)      // 14832

__global__ void prep_k(const float* __restrict__ q,
                       const float* __restrict__ w0, const float* __restrict__ w1,
                       const float* __restrict__ w2,
                       const float* __restrict__ pos, const float* __restrict__ zero,
                       const float* __restrict__ neg,
                       __half* __restrict__ x)
{
    __shared__ float sred_or_strip[192];
    int bid = blockIdx.x, tid = threadIdx.x;

    if (bid < PREP_RMS){
        // ---- rmsnorm row ----
        int m = bid;
        float4 a = reinterpret_cast<const float4*>(q + (size_t)m*EN)[tid];
        float ss = a.x*a.x + a.y*a.y + a.z*a.z + a.w*a.w;
        #pragma unroll
        for (int o=16;o;o>>=1) ss += __shfl_xor_sync(0xffffffffu, ss, o);
        if ((tid&31)==0) sred_or_strip[tid>>5] = ss;
        __syncthreads();
        if (tid<8){
            float v = sred_or_strip[tid];
            #pragma unroll
            for (int o=4;o;o>>=1) v += __shfl_xor_sync(0xffu, v, o);
            if (tid==0) sred_or_strip[0] = v;
        }
        __syncthreads();
        float inv = 1.0f / (sqrtf(sred_or_strip[0]*(1.0f/EN)) + 1e-8f);
        uint2 w = make_uint2(pkh(a.x*inv, a.y*inv), pkh(a.z*inv, a.w*inv));
        *reinterpret_cast<uint2*>(x + (size_t)m*EN + tid*4) = w;
    } else if (bid < PREP_CVT){
        // ---- weight fp32 -> fp16 ----
        const int per = (D1N*EN)/4;   // 524288 float4 per matrix
        int i = (bid - PREP_RMS)*256 + tid;
        int sel = i / per, loc = i - sel*per;
        const float* w = sel==0 ? w0 : (sel==1 ? w1 : w2);
        __half* o      = sel==0 ? g_uw : (sel==1 ? g_vw : g_ow);
        float4 a = reinterpret_cast<const float4*>(w)[loc];
        reinterpret_cast<uint2*>(o)[loc] = make_uint2(pkh(a.x,a.y), pkh(a.z,a.w));
    } else {
        // ---- toeplitz tile build ----
        int t = bid - PREP_CVT;          // 0..495
        int ti = t % 62, h = t / 62;
        float* sT = sred_or_strip;
        if (tid < 191){
            int r = (ti-31)*64 + tid - 63;
            float v;
            if (r > 0)      v = pos[h*(LN-1) + r - 1];
            else if (r < 0) v = neg[h*(LN-1) - r - 1];
            else            v = zero[h];
            sT[tid] = v;
        }
        __syncthreads();
        char* dst = (char*)g_tt + (((size_t)h*62 + ti)*8192)*2;
        #pragma unroll
        for (int it=0;it<4;it++){
            int idx = it*256+tid, m = idx>>3, k8 = (idx&7)<<3;
            int base = m + 63 - k8;
            uint32_t so = SWZ(m*128 + k8*2);
            uint32_t v0 = pkh(sT[base],   sT[base-1]);
            uint32_t v1 = pkh(sT[base-2], sT[base-3]);
            uint32_t v2 = pkh(sT[base-4], sT[base-5]);
            uint32_t v3 = pkh(sT[base-6], sT[base-7]);
            *(uint4*)(dst+so) = make_uint4(v0,v1,v2,v3);
        }
    }
}

// ---------------------------------------------------------------------------
// MMA core: 128x128 tile, 8 warps as 2(m)x4(n), warp tile 64x32.  (R13 form)
// ---------------------------------------------------------------------------
struct Acc { float a[4][4][4]; };

__device__ __forceinline__ void mma_stage(Acc& A, uint32_t base, int wm0, int wn0, int lid)
{
    int g = lid>>3;
    #pragma unroll
    for (int ks=0;ks<4;ks++){
        uint32_t af[4][4], bf_[2][4];
        int arow = ((lid>>3)&1)*8 + (lid&7);
        int acol = ks*16 + ((lid>>4)&1)*8;
        #pragma unroll
        for (int mi=0;mi<4;mi++)
            ldsm4(af[mi], base+TA_+SWZ((wm0+mi*16+arow)*128 + acol*2));
        int brow = (g>>1)*8 + (lid&7);
        int bcol = ks*16 + (g&1)*8;
        #pragma unroll
        for (int np=0;np<2;np++)
            ldsm4(bf_[np], base+TB_+SWZ((wn0+np*16+brow)*128 + bcol*2));
        #pragma unroll
        for (int mi=0;mi<4;mi++)
            #pragma unroll
            for (int np=0;np<2;np++){
                mma16816(A.a[mi][2*np+0], af[mi], &bf_[np][0]);
                mma16816(A.a[mi][2*np+1], af[mi], &bf_[np][2]);
            }
    }
}

#define ACC_INIT(acc) \
    _Pragma("unroll") for (int i=0;i<4;i++) \
    _Pragma("unroll") for (int j=0;j<4;j++) \
    _Pragma("unroll") for (int r=0;r<4;r++) acc.a[i][j][r] = 0.f;

// ---------------------------------------------------------------------------
// Pipelined fp16 GEMM, tile 128x128, K-chunk 64, 3-stage cp.async.
// EPI 0: silu(acc+bias) -> f16 row-major.
// EPI 1: acc+bias+resid -> f32 row-major.
// EPI 2: silu(acc+bias) -> f16 written TRANSPOSED into vt layout
//        [(h*4+b)*256+d][l]  (m = l*4+b, n = h*256+d).
// ---------------------------------------------------------------------------
template<int EPI>
__global__ void __launch_bounds__(256, 2)
gemm_k(const __half* __restrict__ Ah, const __half* __restrict__ Bh,
       const float* __restrict__ bias, const float* __restrict__ resid,
       void* __restrict__ Cv, int K, int Nld)
{
    extern __shared__ char smem[];
    const uint32_t sb = smem_u32(smem);
    int tid = threadIdx.x, wid = tid>>5, lid = tid&31;
    int i0 = blockIdx.y*128, n0 = blockIdx.x*128;
    int wm0 = (wid>>2)*64, wn0 = (wid&3)*32;
    Acc acc; ACC_INIT(acc);

    int lr = tid>>3, lq = tid&7;
    uint32_t soT = SWZ(lr*128 + lq*16);

    auto load_chunk = [&](int c, int st){
        uint32_t bs = sb + st*STG;
        int kt = c<<6;
        #pragma unroll
        for (int it=0;it<4;it++){
            int r = lr + it*32;
            uint32_t so = soT + it*(32*128);
            cpa16(bs+TA_+so, Ah + (size_t)(i0 + r)*K + kt + lq*8);
            cpa16(bs+TB_+so, Bh + (size_t)(n0 + r)*K + kt + lq*8);
        }
        cpa_commit();
    };

    const int nch = K>>6;
    load_chunk(0, 0);
    if (nch > 1) load_chunk(1, 1);
    for (int c=0;c<nch;c++){
        if (c+1 < nch) cpa_wait1(); else cpa_wait0();
        __syncthreads();
        if (c+2 < nch) load_chunk(c+2, (c+2)%3);
        mma_stage(acc, sb + (c%3)*STG, wm0, wn0, lid);
    }

    if (EPI==2){
        // stage silu output into smem (row stride 136 halves), then write transposed
        __syncthreads();   // everyone done reading fragments
        __half* ts = (__half*)smem;
        #pragma unroll
        for (int mi=0;mi<4;mi++)
            #pragma unroll
            for (int ni=0;ni<4;ni++){
                int nn = wn0 + ni*8 + 2*(lid&3);
                #pragma unroll
                for (int half_=0;half_<2;half_++){
                    int ml = wm0 + mi*16 + (lid>>2) + half_*8;
                    float s0 = acc.a[mi][ni][2*half_+0] + bias[n0+nn];
                    float s1 = acc.a[mi][ni][2*half_+1] + bias[n0+nn+1];
                    s0 = s0 / (1.0f + __expf(-s0));
                    s1 = s1 / (1.0f + __expf(-s1));
                    *(uint32_t*)(ts + ml*136 + nn) = pkh(s0, s1);
                }
            }
        __syncthreads();
        int h = n0 >> 8, dbase = n0 & 255;
        int l0 = i0 >> 2;                      // 32-aligned
        __half* Vt = (__half*)Cv;
        #pragma unroll
        for (int k=0;k<2;k++){
            int idx = tid + k*256;             // 0..511 -> (b, n_local)
            int nl = idx & 127, b = idx >> 7;
            uint32_t buf[16];
            #pragma unroll
            for (int w=0;w<16;w++){
                __half a = ts[((2*w  )*4 + b)*136 + nl];
                __half c = ts[((2*w+1)*4 + b)*136 + nl];
                buf[w] = (uint32_t)__half_as_ushort(a) | ((uint32_t)__half_as_ushort(c)<<16);
            }
            size_t off = ((size_t)(h*4 + b)*HDN + dbase + nl)*LN + l0;
            uint4* dp = (uint4*)(Vt + off);
            #pragma unroll
            for (int w=0;w<4;w++) dp[w] = make_uint4(buf[4*w],buf[4*w+1],buf[4*w+2],buf[4*w+3]);
        }
        return;
    }

    #pragma unroll
    for (int mi=0;mi<4;mi++)
        #pragma unroll
        for (int ni=0;ni<4;ni++){
            int nn = n0 + wn0 + ni*8 + 2*(lid&3);
            #pragma unroll
            for (int half_=0;half_<2;half_++){
                int m = i0 + wm0 + mi*16 + (lid>>2) + half_*8;
                float v0 = acc.a[mi][ni][2*half_+0], v1 = acc.a[mi][ni][2*half_+1];
                if (EPI==0){
                    float s0 = v0 + bias[nn], s1 = v1 + bias[nn+1];
                    s0 = s0 / (1.0f + __expf(-s0)); s1 = s1 / (1.0f + __expf(-s1));
                    *(uint32_t*)((__half*)Cv + (size_t)m*Nld + nn) = pkh(s0, s1);
                } else {
                    const float* rp = resid + (size_t)m*Nld + nn;
                    float o0 = v0 + bias[nn] + rp[0], o1 = v1 + bias[nn+1] + rp[1];
                    *(float2*)((float*)Cv + (size_t)m*Nld + nn) = make_float2(o0, o1);
                }
            }
        }
}

// ---------------------------------------------------------------------------
// Pipelined toeplitz GEMM: A from precomputed f16 tiles, B from vt.
// Tile 128(l) x 128(d), K-chunk 64 over j, 32 chunks, fused gating epilogue.
// ---------------------------------------------------------------------------
__global__ void __launch_bounds__(256, 2)
toep_k(const __half* __restrict__ Vt, const __half* __restrict__ U,
       __half* __restrict__ Ao)
{
    extern __shared__ char smem[];
    const uint32_t sb = smem_u32(smem);
    int tid = threadIdx.x, wid = tid>>5, lid = tid&31;
    int s = blockIdx.z, h = s>>2, b = s&3;
    int i0 = blockIdx.y*128;
    int d0 = blockIdx.x*128;
    int wm0 = (wid>>2)*64, wn0 = (wid&3)*32;
    const __half* vt = Vt + (size_t)s*HDN*LN + (size_t)d0*LN;
    Acc acc; ACC_INIT(acc);

    int lr = tid>>3, lq = tid&7;
    uint32_t soT = SWZ(lr*128 + lq*16);
    int tibase = (blockIdx.y<<1) + 31;

    auto load_chunk = [&](int c, int st){
        uint32_t bs = sb + st*STG;
        int j0 = c<<6;
        const char* th = (const char*)g_tt + (((size_t)h*62 + (tibase - c))*8192)*2;
        #pragma unroll
        for (int it=0;it<4;it++){
            uint32_t lin = (uint32_t)(it*256+tid)*16;   // verbatim 16KB tile copy
            cpa16(bs+TA_+lin, th+lin);
            int r = lr + it*32;
            uint32_t so = soT + it*(32*128);
            cpa16(bs+TB_+so, vt + (size_t)r*LN + j0 + lq*8);
        }
        cpa_commit();
    };

    load_chunk(0, 0);
    load_chunk(1, 1);
    for (int c=0;c<32;c++){
        if (c+1 < 32) cpa_wait1(); else cpa_wait0();
        __syncthreads();
        if (c+2 < 32) load_chunk(c+2, (c+2)%3);
        mma_stage(acc, sb + (c%3)*STG, wm0, wn0, lid);
    }

    #pragma unroll
    for (int mi=0;mi<4;mi++)
        #pragma unroll
        for (int ni=0;ni<4;ni++){
            int d = d0 + wn0 + ni*8 + 2*(lid&3);
            #pragma unroll
            for (int half_=0;half_<2;half_++){
                int m = i0 + wm0 + mi*16 + (lid>>2) + half_*8;
                size_t off = ((size_t)m*BN_ + b)*D1N + h*HDN + d;
                __half2 u2 = *(const __half2*)(U + off);
                float a0 = acc.a[mi][ni][2*half_+0] * __half2float(u2.x);
                float a1 = acc.a[mi][ni][2*half_+1] * __half2float(u2.y);
                *(uint32_t*)(Ao + off) = pkh(a0, a1);
            }
        }
}

// ---------------------------------------------------------------------------
extern "C" void kernel_launch(void* const* d_in, const int* in_sizes, int n_in,
                              void* d_out, int out_size)
{
    const float* q   = (const float*)d_in[0];
    const float* u_w = (const float*)d_in[3];
    const float* u_b = (const float*)d_in[4];
    const float* v_w = (const float*)d_in[5];
    const float* v_b = (const float*)d_in[6];
    const float* o_w = (const float*)d_in[7];
    const float* o_b = (const float*)d_in[8];
    const float* pos = (const float*)d_in[9];
    const float* zer = (const float*)d_in[10];
    const float* neg = (const float*)d_in[11];
    float* out = (float*)d_out;

    cudaFuncSetAttribute(gemm_k<0>, cudaFuncAttributeMaxDynamicSharedMemorySize, SMEM_SZ);
    cudaFuncSetAttribute(gemm_k<1>, cudaFuncAttributeMaxDynamicSharedMemorySize, SMEM_SZ);
    cudaFuncSetAttribute(gemm_k<2>, cudaFuncAttributeMaxDynamicSharedMemorySize, SMEM_SZ);
    cudaFuncSetAttribute(toep_k,    cudaFuncAttributeMaxDynamicSharedMemorySize, SMEM_SZ);

    void *p;
    #define SYM(v, sym) cudaGetSymbolAddress(&p, sym); auto* v = (decltype(&sym[0]))p;
    SYM(xg,  g_x);
    SYM(uw,  g_uw); SYM(vw,  g_vw); SYM(ow,  g_ow);
    SYM(ug,  g_u);
    SYM(vt,  g_vt); SYM(ag,  g_a);
    #undef SYM

    // fused prep: rmsnorm + 3x weight convert + toeplitz tiles, one launch
    prep_k<<<PREP_TT, 256>>>(q, u_w, v_w, o_w, pos, zer, neg, xg);
    gemm_k<0><<<dim3(D1N/128, MN/128), 256, SMEM_SZ>>>(xg, uw, u_b, nullptr, ug, EN, D1N);
    gemm_k<2><<<dim3(D1N/128, MN/128), 256, SMEM_SZ>>>(xg, vw, v_b, nullptr, vt, EN, D1N);
    toep_k<<<dim3(HDN/128, LN/128, 32), 256, SMEM_SZ>>>(vt, ug, ag);
    gemm_k<1><<<dim3(EN/128, MN/128), 256, SMEM_SZ>>>(ag, ow, o_b, q, out, D1N, EN);
}